// round 1
// baseline (speedup 1.0000x reference)
#include <cuda_runtime.h>
#include <math.h>

// Problem constants
#define DIMV       512
#define HEADS      8
#define DIM_KEY    32
#define NUM_KEYS   256
#define TOPK       16
#define MAX_TOKENS 1024

// scratch for q = (x @ w_q) * 1/sqrt(1+1e-5)
__device__ float g_q[MAX_TOKENS * DIMV];

// ---------------------------------------------------------------------------
// Kernel 1: q = x @ w_q, scaled. C[M=tokens, N=512], K=512.
// Tiled GEMM: BM=64, BN=64, BK=16, 256 threads, 4x4 per thread.
// ---------------------------------------------------------------------------
__global__ void gemm_q_kernel(const float* __restrict__ A,
                              const float* __restrict__ B)
{
    const int BM = 64, BN = 64, BK = 16;
    __shared__ float As[BK][BM];
    __shared__ float Bs[BK][BN];

    int tid = threadIdx.x;           // 0..255
    int tx = tid & 15;               // 0..15
    int ty = tid >> 4;               // 0..15
    int m0 = blockIdx.y * BM;
    int n0 = blockIdx.x * BN;

    float cr[4][4];
#pragma unroll
    for (int i = 0; i < 4; i++)
#pragma unroll
        for (int j = 0; j < 4; j++) cr[i][j] = 0.0f;

    for (int k0 = 0; k0 < DIMV; k0 += BK) {
#pragma unroll
        for (int i = 0; i < 4; i++) {
            int idx = tid + i * 256;       // 0..1023
            int r = idx >> 4;              // row in tile
            int k = idx & 15;              // k in tile
            As[k][r] = A[(m0 + r) * DIMV + k0 + k];
        }
#pragma unroll
        for (int i = 0; i < 4; i++) {
            int idx = tid + i * 256;
            int c = idx & 63;
            int k = idx >> 6;
            Bs[k][c] = B[(k0 + k) * DIMV + n0 + c];
        }
        __syncthreads();
#pragma unroll
        for (int k = 0; k < BK; k++) {
            float4 a4 = *reinterpret_cast<const float4*>(&As[k][ty * 4]);
            float4 b4 = *reinterpret_cast<const float4*>(&Bs[k][tx * 4]);
            float a[4] = {a4.x, a4.y, a4.z, a4.w};
            float b[4] = {b4.x, b4.y, b4.z, b4.w};
#pragma unroll
            for (int i = 0; i < 4; i++)
#pragma unroll
                for (int j = 0; j < 4; j++) cr[i][j] += a[i] * b[j];
        }
        __syncthreads();
    }

    const float scale = 0.99999500003749981f;  // 1/sqrt(1+1e-5)
#pragma unroll
    for (int i = 0; i < 4; i++) {
        int row = m0 + ty * 4 + i;
#pragma unroll
        for (int j = 0; j < 4; j++) {
            g_q[row * DIMV + n0 + tx * 4 + j] = cr[i][j] * scale;
        }
    }
}

// ---------------------------------------------------------------------------
// Kernel 2: per-token PEER: sim -> top16 -> combined top16 -> softmax ->
//           down dots -> gelu -> up accumulation.
// One block per token, 256 threads.
// ---------------------------------------------------------------------------
__device__ __forceinline__ float gelu_tanh(float x) {
    float x3 = x * x * x;
    float t = tanhf(0.7978845608028654f * (x + 0.044715f * x3));
    return 0.5f * x * (1.0f + t);
}

// top-16 selection over val[0..255]: value desc, index asc tie-break.
// Destroys val (selected entries set to -inf). ov/oi get rank-ordered results.
__device__ __forceinline__ void top16_select(
    float* val, float* ov, int* oi,
    float* wv, int* wi, int tid)
{
    int w = tid >> 5, lane = tid & 31;
    for (int r = 0; r < TOPK; r++) {
        float v = val[tid];
        int idx = tid;
#pragma unroll
        for (int off = 16; off > 0; off >>= 1) {
            float v2 = __shfl_down_sync(0xffffffffu, v, off);
            int i2 = __shfl_down_sync(0xffffffffu, idx, off);
            if (v2 > v || (v2 == v && i2 < idx)) { v = v2; idx = i2; }
        }
        if (lane == 0) { wv[w] = v; wi[w] = idx; }
        __syncthreads();
        if (tid == 0) {
            float bv = wv[0]; int bi = wi[0];
#pragma unroll
            for (int x = 1; x < 8; x++) {
                if (wv[x] > bv || (wv[x] == bv && wi[x] < bi)) { bv = wv[x]; bi = wi[x]; }
            }
            ov[r] = bv;
            oi[r] = bi;
            val[bi] = -INFINITY;
        }
        __syncthreads();
    }
}

__global__ void peer_main_kernel(const float* __restrict__ keys,
                                 const float* __restrict__ wdown,
                                 const float* __restrict__ wup,
                                 float* __restrict__ out)
{
    int t = blockIdx.x;
    int tid = threadIdx.x;  // 0..255
    int w = tid >> 5, lane = tid & 31;

    __shared__ float qs[DIMV];
    __shared__ float val[NUM_KEYS];
    __shared__ float acc[DIMV];
    __shared__ float v0[TOPK];
    __shared__ int   i0[TOPK];
    __shared__ float scf[TOPK];
    __shared__ int   pk[TOPK];
    __shared__ float wsm[TOPK];
    __shared__ float hw[TOPK];
    __shared__ float wv[8];
    __shared__ int   wi[8];

    qs[tid]       = g_q[t * DIMV + tid];
    qs[tid + 256] = g_q[t * DIMV + 256 + tid];
    acc[tid] = 0.0f;
    acc[tid + 256] = 0.0f;
    __syncthreads();

    for (int h = 0; h < HEADS; h++) {
        // ---- sim[k] = dot(q[h*32 : h*32+32], keys[h][k][0][:]) ----
        {
            const float4* kp = reinterpret_cast<const float4*>(
                keys + (size_t)((h * NUM_KEYS + tid) * 2) * DIM_KEY);
            const float* qh = qs + h * DIM_KEY;
            float s = 0.0f;
#pragma unroll
            for (int v4 = 0; v4 < 8; v4++) {
                float4 kk = kp[v4];
                s += qh[v4 * 4 + 0] * kk.x;
                s += qh[v4 * 4 + 1] * kk.y;
                s += qh[v4 * 4 + 2] * kk.z;
                s += qh[v4 * 4 + 3] * kk.w;
            }
            val[tid] = s;
        }
        __syncthreads();

        // ---- top16 of sim: v0 (values), i0 (indices) ----
        top16_select(val, v0, i0, wv, wi, tid);

        // ---- combined scores: c[i*16+j] = v0[i] + float(i0[j]) ----
        val[tid] = v0[tid >> 4] + (float)i0[tid & 15];
        __syncthreads();

        // ---- top16 of combined: scf (scores), pk (flattened indices) ----
        top16_select(val, scf, pk, wv, wi, tid);

        // ---- softmax over scf (warp 0) ----
        if (tid < 32) {
            float v = (tid < TOPK) ? scf[tid] : -INFINITY;
            float m = v;
#pragma unroll
            for (int off = 16; off > 0; off >>= 1)
                m = fmaxf(m, __shfl_xor_sync(0xffffffffu, m, off));
            float e = (tid < TOPK) ? expf(v - m) : 0.0f;
            float s = e;
#pragma unroll
            for (int off = 16; off > 0; off >>= 1)
                s += __shfl_xor_sync(0xffffffffu, s, off);
            if (tid < TOPK) wsm[tid] = e / s;
        }
        __syncthreads();

        // ---- down dots: hw[r] = gelu(dot(q, down[pk[r]])) * wsm[r] ----
        // 8 warps x 2 experts each
#pragma unroll
        for (int rr = 0; rr < 2; rr++) {
            int r = w * 2 + rr;
            int e = pk[r];
            const float* dp = wdown + (size_t)e * DIMV;
            float s = 0.0f;
#pragma unroll
            for (int s2 = 0; s2 < 16; s2++) {
                int d = lane + 32 * s2;
                s += qs[d] * dp[d];
            }
#pragma unroll
            for (int off = 16; off > 0; off >>= 1)
                s += __shfl_xor_sync(0xffffffffu, s, off);
            if (lane == 0) hw[r] = gelu_tanh(s) * wsm[r];
        }
        __syncthreads();

        // ---- up accumulation: acc[d] += sum_r hw[r]*up[pk[r]][d] ----
        float a0 = 0.0f, a1 = 0.0f;
#pragma unroll
        for (int r = 0; r < TOPK; r++) {
            float wgt = hw[r];
            const float* upr = wup + (size_t)pk[r] * DIMV;
            a0 += wgt * upr[tid];
            a1 += wgt * upr[tid + 256];
        }
        acc[tid] += a0;
        acc[tid + 256] += a1;
        __syncthreads();
    }

    out[t * DIMV + tid]       = acc[tid];
    out[t * DIMV + 256 + tid] = acc[tid + 256];
}

// ---------------------------------------------------------------------------
extern "C" void kernel_launch(void* const* d_in, const int* in_sizes, int n_in,
                              void* d_out, int out_size)
{
    const float* x     = (const float*)d_in[0];   // [b, n, 512]
    const float* w_q   = (const float*)d_in[1];   // [512, 512]
    const float* keys  = (const float*)d_in[2];   // [8, 256, 2, 32]
    const float* wdown = (const float*)d_in[3];   // [65536, 512]
    const float* wup   = (const float*)d_in[4];   // [65536, 512]
    float* out = (float*)d_out;

    int tokens = in_sizes[0] / DIMV;              // 1024

    dim3 ggrid(DIMV / 64, tokens / 64);           // (8, 16)
    gemm_q_kernel<<<ggrid, 256>>>(x, w_q);

    peer_main_kernel<<<tokens, 256>>>(keys, wdown, wup, out);
}

// round 2
// speedup vs baseline: 3.2370x; 3.2370x over previous
#include <cuda_runtime.h>
#include <math.h>

#define DIMV       512
#define HEADS      8
#define DIM_KEY    32
#define NUM_KEYS   256
#define TOPK       16
#define TOKENS     1024
#define FULLMASK   0xffffffffu

// scratch
__device__ float g_q[TOKENS * DIMV];                    // 2 MB
__device__ float g_sim[HEADS * TOKENS * NUM_KEYS];      // 8 MB

// ---------------------------------------------------------------------------
// Kernel 1: q = (x @ w_q) * 1/sqrt(1+1e-5). C[M=tokens, N=512], K=512.
// ---------------------------------------------------------------------------
__global__ void gemm_q_kernel(const float* __restrict__ A,
                              const float* __restrict__ B)
{
    const int BM = 64, BN = 64, BK = 16;
    __shared__ float As[BK][BM];
    __shared__ float Bs[BK][BN];

    int tid = threadIdx.x;
    int tx = tid & 15;
    int ty = tid >> 4;
    int m0 = blockIdx.y * BM;
    int n0 = blockIdx.x * BN;

    float cr[4][4];
#pragma unroll
    for (int i = 0; i < 4; i++)
#pragma unroll
        for (int j = 0; j < 4; j++) cr[i][j] = 0.0f;

    for (int k0 = 0; k0 < DIMV; k0 += BK) {
#pragma unroll
        for (int i = 0; i < 4; i++) {
            int idx = tid + i * 256;
            int r = idx >> 4;
            int k = idx & 15;
            As[k][r] = A[(m0 + r) * DIMV + k0 + k];
        }
#pragma unroll
        for (int i = 0; i < 4; i++) {
            int idx = tid + i * 256;
            int c = idx & 63;
            int k = idx >> 6;
            Bs[k][c] = B[(k0 + k) * DIMV + n0 + c];
        }
        __syncthreads();
#pragma unroll
        for (int k = 0; k < BK; k++) {
            float4 a4 = *reinterpret_cast<const float4*>(&As[k][ty * 4]);
            float4 b4 = *reinterpret_cast<const float4*>(&Bs[k][tx * 4]);
            float a[4] = {a4.x, a4.y, a4.z, a4.w};
            float b[4] = {b4.x, b4.y, b4.z, b4.w};
#pragma unroll
            for (int i = 0; i < 4; i++)
#pragma unroll
                for (int j = 0; j < 4; j++) cr[i][j] += a[i] * b[j];
        }
        __syncthreads();
    }

    const float scale = 0.99999500003749981f;
#pragma unroll
    for (int i = 0; i < 4; i++) {
        int row = m0 + ty * 4 + i;
#pragma unroll
        for (int j = 0; j < 4; j++)
            g_q[row * DIMV + n0 + tx * 4 + j] = cr[i][j] * scale;
    }
}

// ---------------------------------------------------------------------------
// Kernel 2: g_sim[h][t][k] = dot(q[t, h*32 : h*32+32], keys[h][k][0][:])
// Block = (token-tile of 64, head). Keys tile cached in shared once per block.
// ---------------------------------------------------------------------------
__global__ void sim_kernel(const float* __restrict__ keys)
{
    int h  = blockIdx.y;
    int t0 = blockIdx.x * 64;
    int tid = threadIdx.x;   // 0..255

    __shared__ float Ks[DIM_KEY][NUM_KEYS];   // [d][k] 32 KB
    __shared__ float Qs[DIM_KEY][64];         // [d][t] 8 KB

    // load keys[h][k][0][:] transposed into Ks: thread tid owns key k=tid
    {
        const float4* kp = reinterpret_cast<const float4*>(
            keys + (size_t)((h * NUM_KEYS + tid) * 2) * DIM_KEY);
#pragma unroll
        for (int i = 0; i < 8; i++) {
            float4 f = kp[i];
            Ks[4 * i + 0][tid] = f.x;
            Ks[4 * i + 1][tid] = f.y;
            Ks[4 * i + 2][tid] = f.z;
            Ks[4 * i + 3][tid] = f.w;
        }
    }
    // load q slice transposed: thread handles token tl = tid&63, d-range (tid>>6)*8
    {
        int tl = tid & 63;
        int d0 = (tid >> 6) * 8;
        const float* qp = g_q + (size_t)(t0 + tl) * DIMV + h * DIM_KEY + d0;
        float4 f0 = *reinterpret_cast<const float4*>(qp);
        float4 f1 = *reinterpret_cast<const float4*>(qp + 4);
        Qs[d0 + 0][tl] = f0.x; Qs[d0 + 1][tl] = f0.y;
        Qs[d0 + 2][tl] = f0.z; Qs[d0 + 3][tl] = f0.w;
        Qs[d0 + 4][tl] = f1.x; Qs[d0 + 5][tl] = f1.y;
        Qs[d0 + 6][tl] = f1.z; Qs[d0 + 7][tl] = f1.w;
    }
    __syncthreads();

    // thread computes 4 tokens x 16 keys
    int kg = tid & 15;   // keys kg*16 .. +15
    int tg = tid >> 4;   // tokens tg*4 .. +3
    float acc[4][16];
#pragma unroll
    for (int i = 0; i < 4; i++)
#pragma unroll
        for (int j = 0; j < 16; j++) acc[i][j] = 0.0f;

#pragma unroll
    for (int d = 0; d < DIM_KEY; d++) {
        float4 qv = *reinterpret_cast<const float4*>(&Qs[d][tg * 4]);
        float q4[4] = {qv.x, qv.y, qv.z, qv.w};
        float kv[16];
#pragma unroll
        for (int jj = 0; jj < 4; jj++) {
            float4 kk = *reinterpret_cast<const float4*>(&Ks[d][kg * 16 + jj * 4]);
            kv[jj * 4 + 0] = kk.x; kv[jj * 4 + 1] = kk.y;
            kv[jj * 4 + 2] = kk.z; kv[jj * 4 + 3] = kk.w;
        }
#pragma unroll
        for (int i = 0; i < 4; i++)
#pragma unroll
            for (int j = 0; j < 16; j++) acc[i][j] += q4[i] * kv[j];
    }

#pragma unroll
    for (int i = 0; i < 4; i++) {
        int t = t0 + tg * 4 + i;
        float* op = g_sim + ((size_t)h * TOKENS + t) * NUM_KEYS + kg * 16;
#pragma unroll
        for (int jj = 0; jj < 4; jj++) {
            float4 f;
            f.x = acc[i][jj * 4 + 0]; f.y = acc[i][jj * 4 + 1];
            f.z = acc[i][jj * 4 + 2]; f.w = acc[i][jj * 4 + 3];
            *reinterpret_cast<float4*>(op + jj * 4) = f;
        }
    }
}

// ---------------------------------------------------------------------------
// Kernel 3: per-token PEER, one warp per head.
// ---------------------------------------------------------------------------
__device__ __forceinline__ float gelu_tanh(float x) {
    float x3 = x * x * x;
    float t = tanhf(0.7978845608028654f * (x + 0.044715f * x3));
    return 0.5f * x * (1.0f + t);
}

// Warp top-16 of 256 candidates; candidate p lives at lane (p&31), slot (p>>5).
// Value desc, index asc tie-break. Results uniform across the warp.
__device__ __forceinline__ void warp_top16(float* val, int lane,
                                           float* out_v, int* out_i)
{
#pragma unroll
    for (int r = 0; r < TOPK; r++) {
        float bv = val[0]; int bs = 0;
#pragma unroll
        for (int s = 1; s < 8; s++)
            if (val[s] > bv) { bv = val[s]; bs = s; }
        int bp = lane + (bs << 5);
#pragma unroll
        for (int off = 16; off > 0; off >>= 1) {
            float ov = __shfl_xor_sync(FULLMASK, bv, off);
            int   op = __shfl_xor_sync(FULLMASK, bp, off);
            if (ov > bv || (ov == bv && op < bp)) { bv = ov; bp = op; }
        }
        out_v[r] = bv;
        out_i[r] = bp;
        if ((bp & 31) == lane) {
            int ws = bp >> 5;
#pragma unroll
            for (int s = 0; s < 8; s++)
                if (s == ws) val[s] = -INFINITY;
        }
    }
}

__global__ void peer_main_kernel(const float* __restrict__ wdown,
                                 const float* __restrict__ wup,
                                 float* __restrict__ out)
{
    int t = blockIdx.x;
    int tid = threadIdx.x;       // 0..255
    int w = tid >> 5;            // warp == head
    int lane = tid & 31;
    int h = w;

    __shared__ float qs[DIMV];
    __shared__ float accp[HEADS][DIMV];    // per-head partial outputs
    __shared__ float v0s[HEADS][TOPK];
    __shared__ float i0s[HEADS][TOPK];     // stored as float

    qs[tid]       = g_q[t * DIMV + tid];
    qs[tid + 256] = g_q[t * DIMV + 256 + tid];
    __syncthreads();

    // ---- load sim row: candidate p = lane + 32*s ----
    float val[8];
    {
        const float* simrow = g_sim + ((size_t)h * TOKENS + t) * NUM_KEYS;
#pragma unroll
        for (int s = 0; s < 8; s++)
            val[s] = simrow[lane + (s << 5)];
    }

    // ---- top16 of sim ----
    float v0[TOPK]; int i0[TOPK];
    warp_top16(val, lane, v0, i0);
    if (lane == 0) {
#pragma unroll
        for (int r = 0; r < TOPK; r++) {
            v0s[w][r] = v0[r];
            i0s[w][r] = (float)i0[r];
        }
    }
    __syncwarp();

    // ---- combined candidates: c[p] = v0[p>>4] + float(i0[p&15]) ----
    float val2[8];
#pragma unroll
    for (int s = 0; s < 8; s++) {
        int p = lane + (s << 5);
        val2[s] = v0s[w][p >> 4] + i0s[w][p & 15];
    }

    float scf[TOPK]; int pk[TOPK];
    warp_top16(val2, lane, scf, pk);

    // ---- lane r owns rank r (r < 16) ----
    float myscf = -INFINITY;
    int mypk = 0;
#pragma unroll
    for (int r = 0; r < TOPK; r++) {
        if (lane == r) { myscf = scf[r]; mypk = pk[r]; }
    }

    // softmax pieces (distributed across lanes)
    float m = scf[0];
#pragma unroll
    for (int r = 1; r < TOPK; r++) m = fmaxf(m, scf[r]);
    float mye = expf(myscf - m);       // lanes >= 16 -> exp(-inf) = 0
    float esum = mye;
#pragma unroll
    for (int off = 16; off > 0; off >>= 1)
        esum += __shfl_xor_sync(FULLMASK, esum, off);

    // ---- down dots ----
    const float4* q4p = reinterpret_cast<const float4*>(qs);
    float mydot = 0.0f;
#pragma unroll
    for (int r = 0; r < TOPK; r++) {
        const float4* dp = reinterpret_cast<const float4*>(
            wdown + (size_t)pk[r] * DIMV);
        float s = 0.0f;
#pragma unroll
        for (int v = 0; v < 4; v++) {
            float4 d4 = dp[lane + (v << 5)];
            float4 q4 = q4p[lane + (v << 5)];
            s += d4.x * q4.x + d4.y * q4.y + d4.z * q4.z + d4.w * q4.w;
        }
#pragma unroll
        for (int off = 16; off > 0; off >>= 1)
            s += __shfl_xor_sync(FULLMASK, s, off);
        if (lane == r) mydot = s;
    }

    // gelu + softmax weight (one per lane), then broadcast
    float g = gelu_tanh(mydot) * (mye / esum);
    float hw[TOPK];
#pragma unroll
    for (int r = 0; r < TOPK; r++)
        hw[r] = __shfl_sync(FULLMASK, g, r);

    // ---- up accumulation ----
    float4 a[4];
#pragma unroll
    for (int v = 0; v < 4; v++) { a[v].x = a[v].y = a[v].z = a[v].w = 0.0f; }
#pragma unroll
    for (int r = 0; r < TOPK; r++) {
        float wgt = hw[r];
        const float4* up4 = reinterpret_cast<const float4*>(
            wup + (size_t)pk[r] * DIMV);
#pragma unroll
        for (int v = 0; v < 4; v++) {
            float4 u = up4[lane + (v << 5)];
            a[v].x += wgt * u.x; a[v].y += wgt * u.y;
            a[v].z += wgt * u.z; a[v].w += wgt * u.w;
        }
    }
    float4* accp4 = reinterpret_cast<float4*>(accp[w]);
#pragma unroll
    for (int v = 0; v < 4; v++)
        accp4[lane + (v << 5)] = a[v];

    __syncthreads();

    // ---- reduce partials across heads ----
#pragma unroll
    for (int rep = 0; rep < 2; rep++) {
        int d = tid + rep * 256;
        float s = 0.0f;
#pragma unroll
        for (int ww = 0; ww < HEADS; ww++) s += accp[ww][d];
        out[t * DIMV + d] = s;
    }
}

// ---------------------------------------------------------------------------
extern "C" void kernel_launch(void* const* d_in, const int* in_sizes, int n_in,
                              void* d_out, int out_size)
{
    const float* x     = (const float*)d_in[0];
    const float* w_q   = (const float*)d_in[1];
    const float* keys  = (const float*)d_in[2];
    const float* wdown = (const float*)d_in[3];
    const float* wup   = (const float*)d_in[4];
    float* out = (float*)d_out;

    int tokens = in_sizes[0] / DIMV;   // 1024

    dim3 ggrid(DIMV / 64, tokens / 64);
    gemm_q_kernel<<<ggrid, 256>>>(x, w_q);

    dim3 sgrid(tokens / 64, HEADS);
    sim_kernel<<<sgrid, 256>>>(keys);

    peer_main_kernel<<<tokens, 256>>>(wdown, wup, out);
}